// round 1
// baseline (speedup 1.0000x reference)
#include <cuda_runtime.h>
#include <cstdint>

// Problem: B=4096 poses, N=4096 points each. For each pose:
//   qi = conj(q)/|q|^2 ; p' = qi * p * conj(qi)  (pure quaternion sandwich)
//   pt = p' - trans ; mask = pt inside AABB ; out = -10000 * mean(||pt||) over mask (or 10000 if none)
// Memory-bound: 201 MB streaming read of pc. One CTA per pose, float4-vectorized.

#define NPTS 4096
#define THREADS 256

__global__ __launch_bounds__(THREADS) void collision_dist_kernel(
    const float* __restrict__ trans,   // [B,3]
    const float* __restrict__ quat,    // [B,4]
    const float* __restrict__ pc,      // [B,N,3]
    float* __restrict__ out)           // [B,1]
{
    const int b   = blockIdx.x;
    const int tid = threadIdx.x;

    // ---- per-pose setup (tiny, cached) ----
    const float qx = quat[b * 4 + 0];
    const float qy = quat[b * 4 + 1];
    const float qz = quat[b * 4 + 2];
    const float qw = quat[b * 4 + 3];
    const float s   = qx * qx + qy * qy + qz * qz + qw * qw;
    const float inv = 1.0f / s;
    // qi = conj(q)/s = (tx,ty,tz,tw)
    const float tx = -qx * inv, ty = -qy * inv, tz = -qz * inv, tw = qw * inv;

    // Sandwich t * (v,0) * conj(t) expands to this exact matrix (non-unit t ok):
    const float txx = tx * tx, tyy = ty * ty, tzz = tz * tz, tww = tw * tw;
    const float r00 = tww + txx - tyy - tzz;
    const float r11 = tww - txx + tyy - tzz;
    const float r22 = tww - txx - tyy + tzz;
    const float r01 = 2.0f * (tx * ty - tw * tz);
    const float r02 = 2.0f * (tx * tz + tw * ty);
    const float r10 = 2.0f * (tx * ty + tw * tz);
    const float r12 = 2.0f * (ty * tz - tw * tx);
    const float r20 = 2.0f * (tx * tz - tw * ty);
    const float r21 = 2.0f * (ty * tz + tw * tx);

    const float trx = trans[b * 3 + 0];
    const float try_ = trans[b * 3 + 1];
    const float trz = trans[b * 3 + 2];

    // AABB bounds, computed with identical double->float rounding as numpy
    const float cx = -0.001782f, cy = 1.005e-05f, cz = 0.0431621f;
    const float hx = (float)(0.204416 / 2.0 + 0.001);
    const float hy = (float)(0.0632517 / 2.0 + 0.001);
    const float hz = (float)(0.1381738 / 2.0 + 0.001);
    const float lox = cx - hx, loy = cy - hy, loz = cz - hz;
    const float hix = cx + hx, hiy = cy + hy, hiz = cz + hz;

    // ---- stream the point cloud: 4 points = 3 float4 per group ----
    const float4* __restrict__ row =
        reinterpret_cast<const float4*>(pc + (size_t)b * (size_t)NPTS * 3);

    float sum = 0.0f;
    int   cnt = 0;

    const int ngroups = NPTS / 4;  // 1024
    for (int g = tid; g < ngroups; g += THREADS) {
        const float4 A = row[g * 3 + 0];
        const float4 B = row[g * 3 + 1];
        const float4 C = row[g * 3 + 2];

        float px[4] = {A.x, A.w, B.z, C.y};
        float py[4] = {A.y, B.x, B.w, C.z};
        float pz[4] = {A.z, B.y, C.x, C.w};

#pragma unroll
        for (int k = 0; k < 4; ++k) {
            const float x = px[k], y = py[k], z = pz[k];
            const float rx = r00 * x + r01 * y + r02 * z - trx;
            const float ry = r10 * x + r11 * y + r12 * z - try_;
            const float rz = r20 * x + r21 * y + r22 * z - trz;
            const bool inside =
                (rx >= lox) & (rx <= hix) &
                (ry >= loy) & (ry <= hiy) &
                (rz >= loz) & (rz <= hiz);
            if (inside) {
                sum += sqrtf(rx * rx + ry * ry + rz * rz);
                cnt += 1;
            }
        }
    }

    // ---- block reduction ----
#pragma unroll
    for (int off = 16; off > 0; off >>= 1) {
        sum += __shfl_down_sync(0xFFFFFFFFu, sum, off);
        cnt += __shfl_down_sync(0xFFFFFFFFu, cnt, off);
    }

    __shared__ float s_sum[THREADS / 32];
    __shared__ int   s_cnt[THREADS / 32];
    const int warp = tid >> 5;
    const int lane = tid & 31;
    if (lane == 0) { s_sum[warp] = sum; s_cnt[warp] = cnt; }
    __syncthreads();

    if (warp == 0) {
        float fs = (lane < THREADS / 32) ? s_sum[lane] : 0.0f;
        int   fc = (lane < THREADS / 32) ? s_cnt[lane] : 0;
#pragma unroll
        for (int off = 4; off > 0; off >>= 1) {
            fs += __shfl_down_sync(0xFFFFFFFFu, fs, off);
            fc += __shfl_down_sync(0xFFFFFFFFu, fc, off);
        }
        if (lane == 0) {
            const float dist = (fc > 0) ? (-fs / (float)max(fc, 1)) : 1.0f;
            out[b] = dist * 10000.0f;
        }
    }
}

extern "C" void kernel_launch(void* const* d_in, const int* in_sizes, int n_in,
                              void* d_out, int out_size)
{
    const float* trans = (const float*)d_in[0];  // [4096,3]
    const float* quat  = (const float*)d_in[1];  // [4096,4]
    const float* pc    = (const float*)d_in[2];  // [4096,4096,3]
    float* out = (float*)d_out;                  // [4096,1]

    const int B = in_sizes[0] / 3;  // 4096
    collision_dist_kernel<<<B, THREADS>>>(trans, quat, pc, out);
}

// round 2
// speedup vs baseline: 1.0540x; 1.0540x over previous
#include <cuda_runtime.h>
#include <cstdint>

// B=4096 poses x N=4096 points. Pure HBM streaming reduction (201 MB read).
// One CTA per pose, 256 threads. Each thread owns exactly 4 groups of 4 points
// = 12 float4 loads, ALL issued up front (MLP=12) before any compute, so the
// long-scoreboard latency is covered and DRAM stays saturated.

#define NPTS 4096
#define THREADS 256

__global__ __launch_bounds__(THREADS) void collision_dist_kernel(
    const float* __restrict__ trans,   // [B,3]
    const float* __restrict__ quat,    // [B,4]
    const float* __restrict__ pc,      // [B,N,3]
    float* __restrict__ out)           // [B,1]
{
    const int b   = blockIdx.x;
    const int tid = threadIdx.x;

    // ---- per-pose setup (tiny, L1/L2-resident) ----
    const float qx = quat[b * 4 + 0];
    const float qy = quat[b * 4 + 1];
    const float qz = quat[b * 4 + 2];
    const float qw = quat[b * 4 + 3];
    const float s   = qx * qx + qy * qy + qz * qz + qw * qw;
    const float inv = 1.0f / s;
    // qi = conj(q)/s
    const float tx = -qx * inv, ty = -qy * inv, tz = -qz * inv, tw = qw * inv;

    // Sandwich t*(v,0)*conj(t) as a 3x3 matrix (valid for non-unit t):
    const float txx = tx * tx, tyy = ty * ty, tzz = tz * tz, tww = tw * tw;
    const float r00 = tww + txx - tyy - tzz;
    const float r11 = tww - txx + tyy - tzz;
    const float r22 = tww - txx - tyy + tzz;
    const float r01 = 2.0f * (tx * ty - tw * tz);
    const float r02 = 2.0f * (tx * tz + tw * ty);
    const float r10 = 2.0f * (tx * ty + tw * tz);
    const float r12 = 2.0f * (ty * tz - tw * tx);
    const float r20 = 2.0f * (tx * tz - tw * ty);
    const float r21 = 2.0f * (ty * tz + tw * tx);

    const float trx  = trans[b * 3 + 0];
    const float try_ = trans[b * 3 + 1];
    const float trz  = trans[b * 3 + 2];

    // AABB bounds (double->float rounding identical to numpy reference)
    const float cx = -0.001782f, cy = 1.005e-05f, cz = 0.0431621f;
    const float hx = (float)(0.204416 / 2.0 + 0.001);
    const float hy = (float)(0.0632517 / 2.0 + 0.001);
    const float hz = (float)(0.1381738 / 2.0 + 0.001);
    const float lox = cx - hx, loy = cy - hy, loz = cz - hz;
    const float hix = cx + hx, hiy = cy + hy, hiz = cz + hz;

    const float4* __restrict__ row =
        reinterpret_cast<const float4*>(pc + (size_t)b * (size_t)NPTS * 3);

    // ---- front-batch ALL loads: 4 groups x 3 float4 = 12 loads in flight ----
    float4 v[12];
#pragma unroll
    for (int i = 0; i < 4; ++i) {
        const int g = tid + i * THREADS;          // coalesced across the warp
#pragma unroll
        for (int j = 0; j < 3; ++j)
            v[i * 3 + j] = __ldcs(&row[g * 3 + j]);  // streaming, evict-first
    }

    float sum = 0.0f;
    int   cnt = 0;

#pragma unroll
    for (int i = 0; i < 4; ++i) {
        const float4 A = v[i * 3 + 0];
        const float4 Bv = v[i * 3 + 1];
        const float4 C = v[i * 3 + 2];

        const float px[4] = {A.x, A.w, Bv.z, C.y};
        const float py[4] = {A.y, Bv.x, Bv.w, C.z};
        const float pz[4] = {A.z, Bv.y, C.x, C.w};

#pragma unroll
        for (int k = 0; k < 4; ++k) {
            const float x = px[k], y = py[k], z = pz[k];
            const float rx = fmaf(r00, x, fmaf(r01, y, r02 * z)) - trx;
            const float ry = fmaf(r10, x, fmaf(r11, y, r12 * z)) - try_;
            const float rz = fmaf(r20, x, fmaf(r21, y, r22 * z)) - trz;
            const bool inside =
                (rx >= lox) & (rx <= hix) &
                (ry >= loy) & (ry <= hiy) &
                (rz >= loz) & (rz <= hiz);
            const float nrm = sqrtf(fmaf(rx, rx, fmaf(ry, ry, rz * rz)));
            sum += inside ? nrm : 0.0f;   // predicated, no divergence
            cnt += (int)inside;
        }
    }

    // ---- block reduction ----
#pragma unroll
    for (int off = 16; off > 0; off >>= 1) {
        sum += __shfl_down_sync(0xFFFFFFFFu, sum, off);
        cnt += __shfl_down_sync(0xFFFFFFFFu, cnt, off);
    }

    __shared__ float s_sum[THREADS / 32];
    __shared__ int   s_cnt[THREADS / 32];
    const int warp = tid >> 5;
    const int lane = tid & 31;
    if (lane == 0) { s_sum[warp] = sum; s_cnt[warp] = cnt; }
    __syncthreads();

    if (warp == 0) {
        float fs = (lane < THREADS / 32) ? s_sum[lane] : 0.0f;
        int   fc = (lane < THREADS / 32) ? s_cnt[lane] : 0;
#pragma unroll
        for (int off = 4; off > 0; off >>= 1) {
            fs += __shfl_down_sync(0xFFFFFFFFu, fs, off);
            fc += __shfl_down_sync(0xFFFFFFFFu, fc, off);
        }
        if (lane == 0) {
            const float dist = (fc > 0) ? (-fs / (float)max(fc, 1)) : 1.0f;
            out[b] = dist * 10000.0f;
        }
    }
}

extern "C" void kernel_launch(void* const* d_in, const int* in_sizes, int n_in,
                              void* d_out, int out_size)
{
    const float* trans = (const float*)d_in[0];  // [4096,3]
    const float* quat  = (const float*)d_in[1];  // [4096,4]
    const float* pc    = (const float*)d_in[2];  // [4096,4096,3]
    float* out = (float*)d_out;                  // [4096,1]

    const int B = in_sizes[0] / 3;  // 4096
    collision_dist_kernel<<<B, THREADS>>>(trans, quat, pc, out);
}

// round 3
// speedup vs baseline: 1.0668x; 1.0121x over previous
#include <cuda_runtime.h>
#include <cstdint>

// B=4096 poses x N=4096 points, pure HBM streaming reduction (201 MB).
// WARP-PER-POSE: 512 CTAs x 256 thr = 4096 warps, one pose each -> single
// wave, zero block barriers. Each lane owns 32 chunks of 4 points (3 float4),
// double-buffered so 3 loads are always in flight per warp.

#define NPTS 4096
#define THREADS 256

__device__ __forceinline__ void process4(
    const float4 A, const float4 Bv, const float4 C,
    const float r00, const float r01, const float r02,
    const float r10, const float r11, const float r12,
    const float r20, const float r21, const float r22,
    const float trx, const float try_, const float trz,
    const float lox, const float loy, const float loz,
    const float hix, const float hiy, const float hiz,
    float& sum, int& cnt)
{
    const float px[4] = {A.x, A.w, Bv.z, C.y};
    const float py[4] = {A.y, Bv.x, Bv.w, C.z};
    const float pz[4] = {A.z, Bv.y, C.x, C.w};
#pragma unroll
    for (int k = 0; k < 4; ++k) {
        const float x = px[k], y = py[k], z = pz[k];
        const float rx = fmaf(r00, x, fmaf(r01, y, fmaf(r02, z, -trx)));
        const float ry = fmaf(r10, x, fmaf(r11, y, fmaf(r12, z, -try_)));
        const float rz = fmaf(r20, x, fmaf(r21, y, fmaf(r22, z, -trz)));
        const bool inside =
            (rx >= lox) & (rx <= hix) &
            (ry >= loy) & (ry <= hiy) &
            (rz >= loz) & (rz <= hiz);
        const float nrm = sqrtf(fmaf(rx, rx, fmaf(ry, ry, rz * rz)));
        sum += inside ? nrm : 0.0f;
        cnt += (int)inside;
    }
}

__global__ __launch_bounds__(THREADS, 4) void collision_dist_kernel(
    const float* __restrict__ trans,   // [B,3]
    const float* __restrict__ quat,    // [B,4]
    const float* __restrict__ pc,      // [B,N,3]
    float* __restrict__ out)           // [B,1]
{
    const int lane = threadIdx.x & 31;
    const int b = (blockIdx.x * THREADS + threadIdx.x) >> 5;   // pose = warp id

    // ---- per-pose setup (broadcast loads, L1/L2-resident) ----
    const float qx = __ldg(&quat[b * 4 + 0]);
    const float qy = __ldg(&quat[b * 4 + 1]);
    const float qz = __ldg(&quat[b * 4 + 2]);
    const float qw = __ldg(&quat[b * 4 + 3]);
    const float inv = 1.0f / (qx * qx + qy * qy + qz * qz + qw * qw);
    const float tx = -qx * inv, ty = -qy * inv, tz = -qz * inv, tw = qw * inv;

    const float txx = tx * tx, tyy = ty * ty, tzz = tz * tz, tww = tw * tw;
    const float r00 = tww + txx - tyy - tzz;
    const float r11 = tww - txx + tyy - tzz;
    const float r22 = tww - txx - tyy + tzz;
    const float r01 = 2.0f * (tx * ty - tw * tz);
    const float r02 = 2.0f * (tx * tz + tw * ty);
    const float r10 = 2.0f * (tx * ty + tw * tz);
    const float r12 = 2.0f * (ty * tz - tw * tx);
    const float r20 = 2.0f * (tx * tz - tw * ty);
    const float r21 = 2.0f * (ty * tz + tw * tx);

    const float trx  = __ldg(&trans[b * 3 + 0]);
    const float try_ = __ldg(&trans[b * 3 + 1]);
    const float trz  = __ldg(&trans[b * 3 + 2]);

    // AABB bounds (double->float rounding identical to numpy)
    const float cx = -0.001782f, cy = 1.005e-05f, cz = 0.0431621f;
    const float hx = (float)(0.204416 / 2.0 + 0.001);
    const float hy = (float)(0.0632517 / 2.0 + 0.001);
    const float hz = (float)(0.1381738 / 2.0 + 0.001);
    const float lox = cx - hx, loy = cy - hy, loz = cz - hz;
    const float hix = cx + hx, hiy = cy + hy, hiz = cz + hz;

    const float4* __restrict__ row =
        reinterpret_cast<const float4*>(pc + (size_t)b * (size_t)NPTS * 3);

    // Each lane: 32 chunks; chunk j covers group g = lane + 32*j (4 points).
    // Double-buffered: next chunk's loads issue before current compute.
    float sum = 0.0f;
    int   cnt = 0;

    const float4* p = row + (size_t)lane * 3;
    float4 a0 = __ldcs(p + 0);
    float4 a1 = __ldcs(p + 1);
    float4 a2 = __ldcs(p + 2);

#pragma unroll 4
    for (int j = 0; j < 31; ++j) {
        const float4* q = row + (size_t)(lane + 32 * (j + 1)) * 3;
        const float4 n0 = __ldcs(q + 0);
        const float4 n1 = __ldcs(q + 1);
        const float4 n2 = __ldcs(q + 2);
        process4(a0, a1, a2, r00, r01, r02, r10, r11, r12, r20, r21, r22,
                 trx, try_, trz, lox, loy, loz, hix, hiy, hiz, sum, cnt);
        a0 = n0; a1 = n1; a2 = n2;
    }
    process4(a0, a1, a2, r00, r01, r02, r10, r11, r12, r20, r21, r22,
             trx, try_, trz, lox, loy, loz, hix, hiy, hiz, sum, cnt);

    // ---- warp-only reduction (no smem, no barriers) ----
#pragma unroll
    for (int off = 16; off > 0; off >>= 1) {
        sum += __shfl_down_sync(0xFFFFFFFFu, sum, off);
        cnt += __shfl_down_sync(0xFFFFFFFFu, cnt, off);
    }
    if (lane == 0) {
        const float dist = (cnt > 0) ? (-sum / (float)max(cnt, 1)) : 1.0f;
        out[b] = dist * 10000.0f;
    }
}

extern "C" void kernel_launch(void* const* d_in, const int* in_sizes, int n_in,
                              void* d_out, int out_size)
{
    const float* trans = (const float*)d_in[0];  // [4096,3]
    const float* quat  = (const float*)d_in[1];  // [4096,4]
    const float* pc    = (const float*)d_in[2];  // [4096,4096,3]
    float* out = (float*)d_out;                  // [4096,1]

    const int B = in_sizes[0] / 3;               // 4096 poses
    const int warps_per_cta = THREADS / 32;
    collision_dist_kernel<<<B / warps_per_cta, THREADS>>>(trans, quat, pc, out);
}

// round 4
// speedup vs baseline: 1.1151x; 1.0453x over previous
#include <cuda_runtime.h>
#include <cstdint>

// B=4096 poses x N=4096 points, pure HBM streaming reduction (201 MB).
// ONE WARP PER CTA, ONE POSE PER WARP: 4096 CTAs x 32 threads. Warp-granular
// CTA scheduling balances SMs to 27-28 warps each (vs 24/32 with 8-warp CTAs).
// Distance-2 prefetch pipeline keeps 6 float4 loads in flight per lane.

#define NPTS 4096

__device__ __forceinline__ void process4(
    const float4 A, const float4 Bv, const float4 C,
    const float r00, const float r01, const float r02,
    const float r10, const float r11, const float r12,
    const float r20, const float r21, const float r22,
    const float trx, const float try_, const float trz,
    float& sum, int& cnt)
{
    // AABB bounds as compile-time constants (same double->float rounding as numpy)
    const float lox = (float)(-0.001782 - (0.204416 / 2.0 + 0.001));
    const float hix = (float)(-0.001782 + (0.204416 / 2.0 + 0.001));
    const float loy = (float)(1.005e-05 - (0.0632517 / 2.0 + 0.001));
    const float hiy = (float)(1.005e-05 + (0.0632517 / 2.0 + 0.001));
    const float loz = (float)(0.0431621 - (0.1381738 / 2.0 + 0.001));
    const float hiz = (float)(0.0431621 + (0.1381738 / 2.0 + 0.001));

    const float px[4] = {A.x, A.w, Bv.z, C.y};
    const float py[4] = {A.y, Bv.x, Bv.w, C.z};
    const float pz[4] = {A.z, Bv.y, C.x, C.w};
#pragma unroll
    for (int k = 0; k < 4; ++k) {
        const float x = px[k], y = py[k], z = pz[k];
        const float rx = fmaf(r00, x, fmaf(r01, y, fmaf(r02, z, -trx)));
        const float ry = fmaf(r10, x, fmaf(r11, y, fmaf(r12, z, -try_)));
        const float rz = fmaf(r20, x, fmaf(r21, y, fmaf(r22, z, -trz)));
        const bool inside =
            (rx >= lox) & (rx <= hix) &
            (ry >= loy) & (ry <= hiy) &
            (rz >= loz) & (rz <= hiz);
        const float nrm = sqrtf(fmaf(rx, rx, fmaf(ry, ry, rz * rz)));
        sum += inside ? nrm : 0.0f;
        cnt += (int)inside;
    }
}

__global__ __launch_bounds__(32, 28) void collision_dist_kernel(
    const float* __restrict__ trans,   // [B,3]
    const float* __restrict__ quat,    // [B,4]
    const float* __restrict__ pc,      // [B,N,3]
    float* __restrict__ out)           // [B,1]
{
    const int lane = threadIdx.x;
    const int b    = blockIdx.x;       // one pose per warp/CTA

    // ---- per-pose setup (broadcast, L1/L2-resident) ----
    const float qx = __ldg(&quat[b * 4 + 0]);
    const float qy = __ldg(&quat[b * 4 + 1]);
    const float qz = __ldg(&quat[b * 4 + 2]);
    const float qw = __ldg(&quat[b * 4 + 3]);
    const float inv = 1.0f / (qx * qx + qy * qy + qz * qz + qw * qw);
    const float tx = -qx * inv, ty = -qy * inv, tz = -qz * inv, tw = qw * inv;

    const float txx = tx * tx, tyy = ty * ty, tzz = tz * tz, tww = tw * tw;
    const float r00 = tww + txx - tyy - tzz;
    const float r11 = tww - txx + tyy - tzz;
    const float r22 = tww - txx - tyy + tzz;
    const float r01 = 2.0f * (tx * ty - tw * tz);
    const float r02 = 2.0f * (tx * tz + tw * ty);
    const float r10 = 2.0f * (tx * ty + tw * tz);
    const float r12 = 2.0f * (ty * tz - tw * tx);
    const float r20 = 2.0f * (tx * tz - tw * ty);
    const float r21 = 2.0f * (ty * tz + tw * tx);

    const float trx  = __ldg(&trans[b * 3 + 0]);
    const float try_ = __ldg(&trans[b * 3 + 1]);
    const float trz  = __ldg(&trans[b * 3 + 2]);

    const float4* __restrict__ row =
        reinterpret_cast<const float4*>(pc + (size_t)b * (size_t)NPTS * 3);

    // Lane owns 32 chunks (4 points = 3 float4 each): group g = lane + 32*j.
    // Distance-2 software pipeline: 6 float4 in flight per lane.
    float sum = 0.0f;
    int   cnt = 0;

    float4 buf[2][3];
    {
        const float4* p0 = row + (size_t)lane * 3;
        const float4* p1 = row + (size_t)(lane + 32) * 3;
        buf[0][0] = __ldcs(p0 + 0); buf[0][1] = __ldcs(p0 + 1); buf[0][2] = __ldcs(p0 + 2);
        buf[1][0] = __ldcs(p1 + 0); buf[1][1] = __ldcs(p1 + 1); buf[1][2] = __ldcs(p1 + 2);
    }

#pragma unroll 2
    for (int j = 0; j < 30; ++j) {
        const float4 A  = buf[j & 1][0];
        const float4 Bv = buf[j & 1][1];
        const float4 C  = buf[j & 1][2];
        const float4* q = row + (size_t)(lane + 32 * (j + 2)) * 3;
        buf[j & 1][0] = __ldcs(q + 0);
        buf[j & 1][1] = __ldcs(q + 1);
        buf[j & 1][2] = __ldcs(q + 2);
        process4(A, Bv, C, r00, r01, r02, r10, r11, r12, r20, r21, r22,
                 trx, try_, trz, sum, cnt);
    }
    process4(buf[0][0], buf[0][1], buf[0][2], r00, r01, r02, r10, r11, r12,
             r20, r21, r22, trx, try_, trz, sum, cnt);
    process4(buf[1][0], buf[1][1], buf[1][2], r00, r01, r02, r10, r11, r12,
             r20, r21, r22, trx, try_, trz, sum, cnt);

    // ---- warp reduction (no smem, no barriers) ----
#pragma unroll
    for (int off = 16; off > 0; off >>= 1) {
        sum += __shfl_down_sync(0xFFFFFFFFu, sum, off);
        cnt += __shfl_down_sync(0xFFFFFFFFu, cnt, off);
    }
    if (lane == 0) {
        const float dist = (cnt > 0) ? (-sum / (float)max(cnt, 1)) : 1.0f;
        out[b] = dist * 10000.0f;
    }
}

extern "C" void kernel_launch(void* const* d_in, const int* in_sizes, int n_in,
                              void* d_out, int out_size)
{
    const float* trans = (const float*)d_in[0];  // [4096,3]
    const float* quat  = (const float*)d_in[1];  // [4096,4]
    const float* pc    = (const float*)d_in[2];  // [4096,4096,3]
    float* out = (float*)d_out;                  // [4096,1]

    const int B = in_sizes[0] / 3;               // 4096 poses
    collision_dist_kernel<<<B, 32>>>(trans, quat, pc, out);
}